// round 16
// baseline (speedup 1.0000x reference)
#include <cuda_runtime.h>

// CapsuleConv2d fused, round 16: f-row ownership + f32x2 packed math + 256-thr CTA.
// N=4, C=64, H=W=32, O=8, L=16, G=8, P=8, F=72, Ho=Wo=32, NUM_ITERS=3.
// CTA 256 thr = 8 warps; warp w covers pos 4w..4w+3 (full 32-pos row);
// lane = (slot 0-7, pid 0-3); lane owns pos and f-rows 9*slot..9*slot+8, all 16 l.
// Priors/routing accumulators packed as f32x2 (l-pairs) -> FFMA2.
// grid = (128 rows, 8 o).
//
// Shared (floats), single phase, 28064 = 109.6 KB:
//   w_s  [72 f][132] rows: [k=l/2 (8)][p (8)][e=l&1 (2)] + 4 pad  @0     (9504)
//   win_s[32 pos](580)[72 f][8 p]                                 @9504  (18560)
#define WIN_OFF    9504
#define WIN_STRIDE 580
#define SM_FLOATS  28064

typedef unsigned long long ull;

__device__ __forceinline__ ull pack2(float a, float b) {
    ull r; asm("mov.b64 %0, {%1, %2};" : "=l"(r) : "f"(a), "f"(b)); return r;
}
__device__ __forceinline__ float2 unpack2(ull a) {
    float x, y; asm("mov.b64 {%0, %1}, %2;" : "=f"(x), "=f"(y) : "l"(a));
    return make_float2(x, y);
}
__device__ __forceinline__ ull fma2(ull a, ull b, ull c) {
    ull d; asm("fma.rn.f32x2 %0, %1, %2, %3;" : "=l"(d) : "l"(a), "l"(b), "l"(c));
    return d;
}
__device__ __forceinline__ ull add2(ull a, ull b) {
    ull d; asm("add.rn.f32x2 %0, %1, %2;" : "=l"(d) : "l"(a), "l"(b));
    return d;
}

__global__ __launch_bounds__(256, 1)
void caps_kernel(const float* __restrict__ x, const float* __restrict__ w,
                 float* __restrict__ out)
{
    extern __shared__ float sm[];
    float* w_s   = sm;
    float* win_s = sm + WIN_OFF;

    const int tid  = threadIdx.x;
    const int lane = tid & 31;
    const int warp = tid >> 5;            // 0..7
    const int slot = lane & 7;            // f-row group owner
    const int pid  = lane >> 3;           // position within warp
    const int pos  = warp * 4 + pid;      // 0..31
    const int f0   = slot * 9;

    const int o = blockIdx.y;
    const int n = blockIdx.x >> 5;
    const int y = blockIdx.x & 31;

    // ---- stage weights transposed to [f][k][p][e] via 2x LDG.64 ----
    {
        float4* sw = (float4*)w_s;        // row stride 33 float4
        #pragma unroll
        for (int i = 0; i < 9; i++) {
            int idx = tid + i * 256;      // 0..2303
            int f   = idx >> 5;
            int r   = idx & 31;
            int k   = r >> 2;             // l-pair
            int c   = r & 3;              // p-pair
            const float* gwf = w + o * 9216 + f * 128;
            float2 a = *(const float2*)(gwf + (2 * k) * 8 + 2 * c);
            float2 b = *(const float2*)(gwf + (2 * k + 1) * 8 + 2 * c);
            sw[f * 33 + r] = make_float4(a.x, b.x, a.y, b.y);
        }
    }
    // ---- stage win patches; each of 256 threads owns one (ppos, p) ----
    {
        const int ppos = (tid & 7) | ((tid >> 3) & 24);   // b0-2 + b6-7
        const int p    = (tid >> 3) & 7;
        const int xb   = ppos - 1;
        bool py[3], px[3];
        #pragma unroll
        for (int k = 0; k < 3; k++) {
            py[k] = (unsigned)(y + k - 1) < 32u;
            px[k] = (unsigned)(xb + k) < 32u;
        }
        const float* xpb = x + ((n * 64 + p) * 32 + (y - 1)) * 32 + xb;
        float* wd = win_s + ppos * WIN_STRIDE + p;
        #pragma unroll
        for (int g = 0; g < 8; g++)
            #pragma unroll
            for (int kh = 0; kh < 3; kh++)
                #pragma unroll
                for (int kw = 0; kw < 3; kw++) {
                    float v = 0.0f;
                    if (py[kh] & px[kw]) v = xpb[g * 8192 + kh * 32 + kw];
                    wd[(g * 9 + kh * 3 + kw) * 8] = v;
                }
    }
    __syncthreads();

    // ---- priors: P2[i][k] = packed (l=2k, l=2k+1) dot products, own 9 f-rows ----
    ull P2[9][8];
    {
        const float4* winp = (const float4*)win_s + pos * (WIN_STRIDE / 4);
        #pragma unroll
        for (int i = 0; i < 9; i++) {
            const int f = f0 + i;
            const ulonglong2* wrow = (const ulonglong2*)w_s + f * 33;
            float4 v0 = winp[f * 2];
            float4 v1 = winp[f * 2 + 1];
            ull vp[8];
            vp[0] = pack2(v0.x, v0.x); vp[1] = pack2(v0.y, v0.y);
            vp[2] = pack2(v0.z, v0.z); vp[3] = pack2(v0.w, v0.w);
            vp[4] = pack2(v1.x, v1.x); vp[5] = pack2(v1.y, v1.y);
            vp[6] = pack2(v1.z, v1.z); vp[7] = pack2(v1.w, v1.w);
            #pragma unroll
            for (int k = 0; k < 8; k++) {
                ull acc = 0ull;                        // (0.0f, 0.0f)
                #pragma unroll
                for (int c = 0; c < 4; c++) {
                    ulonglong2 q = wrow[k * 4 + c];
                    acc = fma2(q.x, vp[2 * c],     acc);
                    acc = fma2(q.y, vp[2 * c + 1], acc);
                }
                P2[i][k] = acc;
            }
        }
    }

    // ---- routing: all state in registers; cross-slot via shuffle allreduce ----
    float probs[9];
    #pragma unroll
    for (int i = 0; i < 9; i++) probs[i] = 1.0f;

    float s[16];
    #pragma unroll
    for (int r = 0; r < 3; r++) {
        ull s2[8];
        if (r == 0) {
            #pragma unroll
            for (int k = 0; k < 8; k++) {
                ull acc = P2[0][k];
                #pragma unroll
                for (int i = 1; i < 9; i++) acc = add2(acc, P2[i][k]);
                s2[k] = acc;
            }
        } else {
            ull pk[9];
            #pragma unroll
            for (int i = 0; i < 9; i++) pk[i] = pack2(probs[i], probs[i]);
            #pragma unroll
            for (int k = 0; k < 8; k++) {
                ull acc = 0ull;
                #pragma unroll
                for (int i = 0; i < 9; i++) acc = fma2(P2[i][k], pk[i], acc);
                s2[k] = acc;
            }
        }
        #pragma unroll
        for (int k = 0; k < 8; k++) {
            float2 u = unpack2(s2[k]);
            s[2 * k] = u.x; s[2 * k + 1] = u.y;
        }
        // allreduce over the 8 slots of this pos group (xor 1,2,4 stay in-group)
        #pragma unroll
        for (int d = 1; d < 8; d <<= 1) {
            #pragma unroll
            for (int l = 0; l < 16; l++)
                s[l] += __shfl_xor_sync(0xffffffffu, s[l], d);
        }
        // squash (redundant in every lane)
        float sq = 0.0f;
        #pragma unroll
        for (int l = 0; l < 16; l++) { s[l] *= 0.125f; sq += s[l] * s[l]; }
        float factor = sqrtf(sq) / (1.0f + sq);
        #pragma unroll
        for (int l = 0; l < 16; l++) s[l] *= factor;   // s is now the output vec

        if (r < 2) {
            ull so2[8];
            #pragma unroll
            for (int k = 0; k < 8; k++) so2[k] = pack2(s[2 * k], s[2 * k + 1]);
            #pragma unroll
            for (int i = 0; i < 9; i++) {
                ull d2 = 0ull;
                #pragma unroll
                for (int k = 0; k < 8; k++) d2 = fma2(P2[i][k], so2[k], d2);
                float2 du = unpack2(d2);
                probs[i] += __expf(du.x + du.y);
            }
        }
    }

    // ---- write: lane emits l = 2*slot, 2*slot+1 for its pos ----
    {
        float* ob = out + ((n * 128 + o * 16) * 32 + y) * 32 + pos;
        ob[(2 * slot)     * 1024] = s[2 * slot];
        ob[(2 * slot + 1) * 1024] = s[2 * slot + 1];
    }
}

extern "C" void kernel_launch(void* const* d_in, const int* in_sizes, int n_in,
                              void* d_out, int out_size)
{
    (void)in_sizes; (void)n_in; (void)out_size;
    const float* x = (const float*)d_in[0];
    const float* w = (const float*)d_in[1];
    float* out     = (float*)d_out;

    cudaFuncSetAttribute(caps_kernel, cudaFuncAttributeMaxDynamicSharedMemorySize,
                         SM_FLOATS * 4);
    dim3 grid(128, 8);
    caps_kernel<<<grid, 256, SM_FLOATS * 4>>>(x, w, out);
}